// round 15
// baseline (speedup 1.0000x reference)
#include <cuda_runtime.h>
#include <math.h>

#define BB    16
#define NBB   512
#define KK    32
#define NBLK  (BB * NBB)      /* 8192 (b, nb) blocks */
#define GW    0.3f
#define GRID  512             /* 32 CTAs per batch; 4 CTAs/SM resident */
#define TPB   256
#define CTAB  32              /* CTAs per batch */

/* ---- scratch (device globals; no allocation) ---- */
__device__ float2 g_vp  [NBLK];     /* (cnt_vld, sum_vld_p) */
__device__ float4 g_cta [GRID];     /* per-CTA (bce_sum, bce_cnt, sq, qu) */
__device__ unsigned int g_barA[BB];
__device__ unsigned int g_done = 0;

/* reduce two floats simultaneously: 2 shfl + 1 packed f32x2 add per level */
__device__ __forceinline__ void warp_sum2(float& a, float& b) {
    unsigned long long p;
    asm("mov.b64 %0, {%1, %2};" : "=l"(p) : "f"(a), "f"(b));
    #pragma unroll
    for (int o = 16; o > 0; o >>= 1) {
        unsigned int lo = (unsigned int)p, hi = (unsigned int)(p >> 32);
        lo = __shfl_down_sync(0xFFFFFFFFu, lo, o);
        hi = __shfl_down_sync(0xFFFFFFFFu, hi, o);
        unsigned long long q = ((unsigned long long)hi << 32) | lo;
        asm("add.rn.f32x2 %0, %1, %2;" : "=l"(p) : "l"(p), "l"(q));
    }
    asm("mov.b64 {%0, %1}, %2;" : "=f"(a), "=f"(b) : "l"(p));
}

__device__ __forceinline__ unsigned int arrive_acq_rel(unsigned int* ctr) {
    unsigned int old;
    asm volatile("atom.acq_rel.gpu.add.u32 %0, [%1], 1;"
                 : "=r"(old) : "l"(ctr) : "memory");
    return old;
}

__device__ __forceinline__ unsigned int ld_acquire(const unsigned int* p) {
    unsigned int v;
    asm volatile("ld.acquire.gpu.u32 %0, [%1];" : "=r"(v) : "l"(p) : "memory");
    return v;
}

struct Stats { float svp, sup_, sup2, bce, cnts; };

__device__ __forceinline__ Stats block_stats(const float4& x4, const float4& t4,
                                             const int4& s4, const int4& i4) {
    Stats r = {0.f, 0.f, 0.f, 0.f, 0.f};
    const float xs[4] = {x4.x, x4.y, x4.z, x4.w};
    const float ts[4] = {t4.x, t4.y, t4.z, t4.w};
    const int   ss[4] = {s4.x, s4.y, s4.z, s4.w};
    const int   is_[4]= {i4.x, i4.y, i4.z, i4.w};
    #pragma unroll
    for (int j = 0; j < 4; ++j) {
        const float x  = xs[j];
        const bool  su = ss[j] != 0;
        const bool  ig = is_[j] != 0;
        const bool  vld = !ig;
        const bool  unc = vld && !su;

        const float p = __fdividef(1.0f, 1.0f + __expf(-x));
        if (vld) r.svp += p;
        if (unc) { r.sup_ += p; r.sup2 = fmaf(p, p, r.sup2); }
        /* targets are exactly 0.0 or 1.0: BCE = -log(t ? p : 1-p) */
        if (su)  r.bce -= __logf(ts[j] > 0.5f ? p : 1.0f - p);
        /* pack counts: vld + 256*unc + 65536*sup (sum < 2^24, exact) */
        r.cnts += (vld ? 1.0f : 0.0f) + (unc ? 256.0f : 0.0f) + (su ? 65536.0f : 0.0f);
    }
    return r;
}

__global__ void __launch_bounds__(TPB, 4) fused_kernel(
    const float4* __restrict__ logits,
    const float4* __restrict__ targets,
    const int4*   __restrict__ sup_mask,
    const int4*   __restrict__ ign_mask,
    const int*    __restrict__ kv_indices,
    const int*    __restrict__ kv_num_blocks,
    float*        __restrict__ out)
{
    const int lane = threadIdx.x & 31;
    const int wid  = threadIdx.x >> 5;
    const int cta  = blockIdx.x;
    const int b    = cta >> 5;                   /* batch: 32 CTAs each */
    const int base = b << 9;                     /* batch * 512 */
    const int blk0 = base + ((cta & 31) << 4) + wid * 2;  /* 2 blocks / warp */

    __shared__ float4 sh_vp4[NBB / 2];           /* whole-batch vp table: 4 KB */
    __shared__ float2 sh_bce[8];
    __shared__ float2 sh_sq[16];
    __shared__ float4 sh_fin[8];
    __shared__ int    sh_role;

    float2* sh_vp = reinterpret_cast<float2*>(sh_vp4);

    /* ---- prefetch phase-B operands (latency hides under phase A) ---- */
    const int idx0 = kv_indices[blk0 * KK + lane];
    const int idx1 = kv_indices[(blk0 + 1) * KK + lane];
    const int knb0 = kv_num_blocks[blk0];
    const int knb1 = kv_num_blocks[blk0 + 1];

    /* ============ Phase A: 2 blocks per warp, fully unrolled (MLP=8) ========== */
    Stats A, B;
    {
        const int v0 = blk0 * 32 + lane;
        const int v1 = v0 + 32;

        const float4 xa = logits[v0],   xb = logits[v1];
        const float4 ta = targets[v0],  tb = targets[v1];
        const int4   sa = sup_mask[v0], sb = sup_mask[v1];
        const int4   ia = ign_mask[v0], ib = ign_mask[v1];

        A = block_stats(xa, ta, sa, ia);
        B = block_stats(xb, tb, sb, ib);

        warp_sum2(A.svp,  B.svp);
        warp_sum2(A.sup_, B.sup_);
        warp_sum2(A.sup2, B.sup2);
        warp_sum2(A.bce,  B.bce);
        warp_sum2(A.cnts, B.cnts);

        if (lane == 0) {
            const int ca = (int)A.cnts, cb = (int)B.cnts;
            g_vp[blk0]     = make_float2((float)(ca & 255), A.svp);
            g_vp[blk0 + 1] = make_float2((float)(cb & 255), B.svp);
            sh_bce[wid] = make_float2(A.bce + B.bce, (float)((ca >> 16) + (cb >> 16)));
        }
    }
    __syncthreads();

    /* warp 0: CTA bce reduce (stays in registers), barrier arrive + poll */
    float cta_bs = 0.f, cta_bc = 0.f;
    if (wid == 0) {
        const float2 t = (lane < 8) ? sh_bce[lane] : make_float2(0.f, 0.f);
        cta_bs = t.x; cta_bc = t.y;
        warp_sum2(cta_bs, cta_bc);
        if (lane == 0) {
            const unsigned int old = arrive_acq_rel(&g_barA[b]);
            if (old != CTAB - 1) {
                while (ld_acquire(&g_barA[b]) < CTAB) __nanosleep(32);
            }
        }
    }
    __syncthreads();

    /* ---- stage the whole batch's vp table into smem (coalesced, 1 ld/thread) */
    sh_vp4[threadIdx.x] = reinterpret_cast<const float4*>(g_vp + base)[threadIdx.x];
    __syncthreads();

    /* ============ Phase B: 2 query blocks per warp, all-smem gathers ========= */
    {
        float2 vp0 = sh_vp[idx0];
        float2 vp1 = sh_vp[idx1];

        if (lane >= knb0) { vp0.x = 0.f; vp0.y = 0.f; }
        if (lane >= knb1) { vp1.x = 0.f; vp1.y = 0.f; }
        float cv0 = vp0.x, sp0 = vp0.y, cv1 = vp1.x, sp1 = vp1.y;
        warp_sum2(cv0, sp0);
        warp_sum2(cv1, sp1);

        if (lane == 0) {
            const float qunc0 = (float)(((int)A.cnts >> 8) & 255);
            const float qunc1 = (float)(((int)B.cnts >> 8) & 255);
            const float nm0 = __fdividef(sp0, fmaxf(cv0, 1.0f));
            const float nm1 = __fdividef(sp1, fmaxf(cv1, 1.0f));
            const bool ok0 = (qunc0 > 0.f) && (knb0 > 0) && (cv0 > 0.f);
            const bool ok1 = (qunc1 > 0.f) && (knb1 > 0) && (cv1 > 0.f);
            const float sq0 = A.sup2 - 2.0f * nm0 * A.sup_ + nm0 * nm0 * qunc0;
            const float sq1 = B.sup2 - 2.0f * nm1 * B.sup_ + nm1 * nm1 * qunc1;
            sh_sq[wid * 2]     = make_float2(ok0 ? sq0 : 0.f, ok0 ? qunc0 : 0.f);
            sh_sq[wid * 2 + 1] = make_float2(ok1 ? sq1 : 0.f, ok1 ? qunc1 : 0.f);
        }
    }
    __syncthreads();

    /* warp 0: CTA sq reduce + single STG.128 partial + SINGLE global counter */
    if (wid == 0) {
        const float2 t = (lane < 16) ? sh_sq[lane] : make_float2(0.f, 0.f);
        float sq = t.x, qu = t.y;
        warp_sum2(sq, qu);
        if (lane == 0) {
            g_cta[cta] = make_float4(cta_bs, cta_bc, sq, qu);
            const unsigned int old = arrive_acq_rel(&g_done);
            sh_role = (old == GRID - 1);
        }
    }
    __syncthreads();
    if (!sh_role) return;

    /* ============ Final tail: last CTA, 8 warps in parallel ================== */
    /* warp w owns batches 2w and 2w+1; each batch = 32 CTA partials = 1 LDG.128/lane */
    {
        float bs = 0.f, bc = 0.f, term = 0.f, nv = 0.f;
        #pragma unroll
        for (int t = 0; t < 2; ++t) {
            const int bb = wid * 2 + t;
            const float4 p = g_cta[(bb << 5) + lane];   /* coalesced 512B */
            bs += p.x; bc += p.y;
            float sq = p.z, qu = p.w;
            warp_sum2(sq, qu);                          /* batch totals on lane 0 */
            if (lane == 0) {
                if (qu > 0.f) { term += __fdividef(sq, qu); nv += 1.f; }
            }
        }
        warp_sum2(bs, bc);                              /* warp's bce totals */
        if (lane == 0) sh_fin[wid] = make_float4(bs, bc, term, nv);
    }
    __syncthreads();

    if (wid == 0) {
        float4 f = (lane < 8) ? sh_fin[lane] : make_float4(0.f, 0.f, 0.f, 0.f);
        float bs = f.x, bc = f.y, term = f.z, nv = f.w;
        warp_sum2(bs, bc);
        warp_sum2(term, nv);
        if (lane == 0) {
            const float bce = __fdividef(bs, fmaxf(bc, 1.0f));
            out[0] = bce + GW * __fdividef(term, fmaxf(nv, 1.0f));
            /* self-reset for graph replay (all CTAs already passed counters) */
            #pragma unroll
            for (int i = 0; i < BB; ++i) g_barA[i] = 0;
            g_done = 0;
        }
    }
}

extern "C" void kernel_launch(void* const* d_in, const int* in_sizes, int n_in,
                              void* d_out, int out_size)
{
    const float4* logits        = (const float4*)d_in[0];
    const float4* targets       = (const float4*)d_in[1];
    const int4*   sup_mask      = (const int4*)d_in[2];
    const int4*   ign_mask      = (const int4*)d_in[3];
    const int*    kv_indices    = (const int*)d_in[4];
    const int*    kv_num_blocks = (const int*)d_in[5];
    float* out = (float*)d_out;

    fused_kernel<<<GRID, TPB>>>(logits, targets, sup_mask, ign_mask,
                                kv_indices, kv_num_blocks, out);
}

// round 16
// speedup vs baseline: 1.0025x; 1.0025x over previous
#include <cuda_runtime.h>
#include <math.h>

#define BB    16
#define NBB   512
#define KK    32
#define NBLK  (BB * NBB)      /* 8192 (b, nb) blocks */
#define GW    0.3f
#define GRID  256             /* 16 CTAs per batch; 2 CTAs/SM, single wave */
#define TPB   256
#define CTAB  16              /* CTAs per batch */

/* ---- scratch (device globals; no allocation) ---- */
__device__ float2 g_vp  [NBLK];     /* (cnt_vld, sum_vld_p) */
__device__ float4 g_cta [GRID];     /* per-CTA (bce_sum, bce_cnt, sq, qu) */
__device__ unsigned int g_barA[BB];
__device__ unsigned int g_done = 0;

/* reduce two floats simultaneously: 2 shfl + 1 packed f32x2 add per level */
__device__ __forceinline__ void warp_sum2(float& a, float& b) {
    unsigned long long p;
    asm("mov.b64 %0, {%1, %2};" : "=l"(p) : "f"(a), "f"(b));
    #pragma unroll
    for (int o = 16; o > 0; o >>= 1) {
        unsigned int lo = (unsigned int)p, hi = (unsigned int)(p >> 32);
        lo = __shfl_down_sync(0xFFFFFFFFu, lo, o);
        hi = __shfl_down_sync(0xFFFFFFFFu, hi, o);
        unsigned long long q = ((unsigned long long)hi << 32) | lo;
        asm("add.rn.f32x2 %0, %1, %2;" : "=l"(p) : "l"(p), "l"(q));
    }
    asm("mov.b64 {%0, %1}, %2;" : "=f"(a), "=f"(b) : "l"(p));
}

__device__ __forceinline__ unsigned int arrive_acq_rel(unsigned int* ctr) {
    unsigned int old;
    asm volatile("atom.acq_rel.gpu.add.u32 %0, [%1], 1;"
                 : "=r"(old) : "l"(ctr) : "memory");
    return old;
}

__device__ __forceinline__ unsigned int ld_acquire(const unsigned int* p) {
    unsigned int v;
    asm volatile("ld.acquire.gpu.u32 %0, [%1];" : "=r"(v) : "l"(p) : "memory");
    return v;
}

struct Stats { float svp, sup_, sup2, bce, cnts; };

__device__ __forceinline__ Stats block_stats(const float4& x4, const float4& t4,
                                             const int4& s4, const int4& i4) {
    Stats r = {0.f, 0.f, 0.f, 0.f, 0.f};
    const float xs[4] = {x4.x, x4.y, x4.z, x4.w};
    const float ts[4] = {t4.x, t4.y, t4.z, t4.w};
    const int   ss[4] = {s4.x, s4.y, s4.z, s4.w};
    const int   is_[4]= {i4.x, i4.y, i4.z, i4.w};
    #pragma unroll
    for (int j = 0; j < 4; ++j) {
        const float x  = xs[j];
        const bool  su = ss[j] != 0;
        const bool  ig = is_[j] != 0;
        const bool  vld = !ig;
        const bool  unc = vld && !su;

        const float p = __fdividef(1.0f, 1.0f + __expf(-x));
        if (vld) r.svp += p;
        if (unc) { r.sup_ += p; r.sup2 = fmaf(p, p, r.sup2); }
        /* targets are exactly 0.0 or 1.0: BCE = -log(t ? p : 1-p) */
        if (su)  r.bce -= __logf(ts[j] > 0.5f ? p : 1.0f - p);
        /* pack counts: vld + 256*unc + 65536*sup (sum < 2^24, exact) */
        r.cnts += (vld ? 1.0f : 0.0f) + (unc ? 256.0f : 0.0f) + (su ? 65536.0f : 0.0f);
    }
    return r;
}

__global__ void __launch_bounds__(TPB, 2) fused_kernel(
    const float4* __restrict__ logits,
    const float4* __restrict__ targets,
    const int4*   __restrict__ sup_mask,
    const int4*   __restrict__ ign_mask,
    const int*    __restrict__ kv_indices,
    const int*    __restrict__ kv_num_blocks,
    float*        __restrict__ out)
{
    const int lane = threadIdx.x & 31;
    const int wid  = threadIdx.x >> 5;
    const int cta  = blockIdx.x;
    const int b    = cta >> 4;                   /* batch: 16 CTAs each */
    const int base = b << 9;                     /* batch * 512 */
    const int blk0 = base + ((cta & 15) << 5) + wid * 4;  /* 4 blocks / warp */

    __shared__ float4 sh_vp4[NBB / 2];           /* whole-batch vp table: 4 KB */
    __shared__ float2 sh_bce[8];
    __shared__ float2 sh_sq[32];
    __shared__ float4 sh_fin[8];
    __shared__ int    sh_role;

    float2* sh_vp = reinterpret_cast<float2*>(sh_vp4);

    /* ---- prefetch phase-B operands (latency hides under phase A) ---- */
    const int idx0 = kv_indices[(blk0 + 0) * KK + lane];
    const int idx1 = kv_indices[(blk0 + 1) * KK + lane];
    const int idx2 = kv_indices[(blk0 + 2) * KK + lane];
    const int idx3 = kv_indices[(blk0 + 3) * KK + lane];
    const int knb0 = kv_num_blocks[blk0 + 0];
    const int knb1 = kv_num_blocks[blk0 + 1];
    const int knb2 = kv_num_blocks[blk0 + 2];
    const int knb3 = kv_num_blocks[blk0 + 3];

    /* ============ Phase A: 4 blocks per warp, fully unrolled (MLP=16) ======== */
    Stats S[4];
    {
        const int v0 = blk0 * 32 + lane;

        float4 x[4], t[4];
        int4   s[4], g[4];
        #pragma unroll
        for (int k = 0; k < 4; ++k) {            /* 16 independent LDG.128 */
            x[k] = logits  [v0 + 32 * k];
            t[k] = targets [v0 + 32 * k];
            s[k] = sup_mask[v0 + 32 * k];
            g[k] = ign_mask[v0 + 32 * k];
        }
        #pragma unroll
        for (int k = 0; k < 4; ++k) S[k] = block_stats(x[k], t[k], s[k], g[k]);

        warp_sum2(S[0].svp,  S[1].svp);   warp_sum2(S[2].svp,  S[3].svp);
        warp_sum2(S[0].sup_, S[1].sup_);  warp_sum2(S[2].sup_, S[3].sup_);
        warp_sum2(S[0].sup2, S[1].sup2);  warp_sum2(S[2].sup2, S[3].sup2);
        warp_sum2(S[0].bce,  S[1].bce);   warp_sum2(S[2].bce,  S[3].bce);
        warp_sum2(S[0].cnts, S[1].cnts);  warp_sum2(S[2].cnts, S[3].cnts);

        if (lane == 0) {
            const int c0 = (int)S[0].cnts, c1 = (int)S[1].cnts;
            const int c2 = (int)S[2].cnts, c3 = (int)S[3].cnts;
            /* two STG.128: blocks are contiguous, float2 pairs pack to float4 */
            reinterpret_cast<float4*>(g_vp + blk0)[0] =
                make_float4((float)(c0 & 255), S[0].svp, (float)(c1 & 255), S[1].svp);
            reinterpret_cast<float4*>(g_vp + blk0)[1] =
                make_float4((float)(c2 & 255), S[2].svp, (float)(c3 & 255), S[3].svp);
            sh_bce[wid] = make_float2(S[0].bce + S[1].bce + S[2].bce + S[3].bce,
                (float)((c0 >> 16) + (c1 >> 16) + (c2 >> 16) + (c3 >> 16)));
        }
    }
    __syncthreads();

    /* warp 0: CTA bce reduce (stays in registers), barrier arrive + poll */
    float cta_bs = 0.f, cta_bc = 0.f;
    if (wid == 0) {
        const float2 t = (lane < 8) ? sh_bce[lane] : make_float2(0.f, 0.f);
        cta_bs = t.x; cta_bc = t.y;
        warp_sum2(cta_bs, cta_bc);
        if (lane == 0) {
            const unsigned int old = arrive_acq_rel(&g_barA[b]);
            if (old != CTAB - 1) {
                while (ld_acquire(&g_barA[b]) < CTAB) __nanosleep(32);
            }
        }
    }
    __syncthreads();

    /* ---- stage the whole batch's vp table into smem (coalesced, 1 ld/thread) */
    sh_vp4[threadIdx.x] = reinterpret_cast<const float4*>(g_vp + base)[threadIdx.x];
    __syncthreads();

    /* ============ Phase B: 4 query blocks per warp, all-smem gathers ========= */
    {
        float2 vp0 = sh_vp[idx0];
        float2 vp1 = sh_vp[idx1];
        float2 vp2 = sh_vp[idx2];
        float2 vp3 = sh_vp[idx3];

        if (lane >= knb0) { vp0.x = 0.f; vp0.y = 0.f; }
        if (lane >= knb1) { vp1.x = 0.f; vp1.y = 0.f; }
        if (lane >= knb2) { vp2.x = 0.f; vp2.y = 0.f; }
        if (lane >= knb3) { vp3.x = 0.f; vp3.y = 0.f; }
        float cv0 = vp0.x, sp0 = vp0.y, cv1 = vp1.x, sp1 = vp1.y;
        float cv2 = vp2.x, sp2 = vp2.y, cv3 = vp3.x, sp3 = vp3.y;
        warp_sum2(cv0, sp0);
        warp_sum2(cv1, sp1);
        warp_sum2(cv2, sp2);
        warp_sum2(cv3, sp3);

        if (lane == 0) {
            const float cv[4] = {cv0, cv1, cv2, cv3};
            const float sp[4] = {sp0, sp1, sp2, sp3};
            const int   kn[4] = {knb0, knb1, knb2, knb3};
            #pragma unroll
            for (int k = 0; k < 4; ++k) {
                const float qunc = (float)(((int)S[k].cnts >> 8) & 255);
                const float nm = __fdividef(sp[k], fmaxf(cv[k], 1.0f));
                const bool ok = (qunc > 0.f) && (kn[k] > 0) && (cv[k] > 0.f);
                const float sq = S[k].sup2 - 2.0f * nm * S[k].sup_ + nm * nm * qunc;
                sh_sq[wid * 4 + k] = make_float2(ok ? sq : 0.f, ok ? qunc : 0.f);
            }
        }
    }
    __syncthreads();

    /* warp 0: CTA sq reduce + single STG.128 partial + SINGLE global counter */
    if (wid == 0) {
        const float2 t = sh_sq[lane];              /* exactly 32 entries */
        float sq = t.x, qu = t.y;
        warp_sum2(sq, qu);
        if (lane == 0) {
            g_cta[cta] = make_float4(cta_bs, cta_bc, sq, qu);
            const unsigned int old = arrive_acq_rel(&g_done);
            sh_role = (old == GRID - 1);
        }
    }
    __syncthreads();
    if (!sh_role) return;

    /* ============ Final tail: last CTA, 8 warps in parallel ================== */
    /* warp w owns batches 2w and 2w+1; batch = 16 CTA partials (lanes >=16 zero) */
    {
        float bs = 0.f, bc = 0.f, term = 0.f, nv = 0.f;
        #pragma unroll
        for (int t = 0; t < 2; ++t) {
            const int bb = wid * 2 + t;
            float4 p = make_float4(0.f, 0.f, 0.f, 0.f);
            if (lane < CTAB) p = g_cta[(bb << 4) + lane];   /* coalesced 256B */
            bs += p.x; bc += p.y;
            float sq = p.z, qu = p.w;
            warp_sum2(sq, qu);                          /* batch totals on lane 0 */
            if (lane == 0) {
                if (qu > 0.f) { term += __fdividef(sq, qu); nv += 1.f; }
            }
        }
        warp_sum2(bs, bc);                              /* warp's bce totals */
        if (lane == 0) sh_fin[wid] = make_float4(bs, bc, term, nv);
    }
    __syncthreads();

    if (wid == 0) {
        float4 f = (lane < 8) ? sh_fin[lane] : make_float4(0.f, 0.f, 0.f, 0.f);
        float bs = f.x, bc = f.y, term = f.z, nv = f.w;
        warp_sum2(bs, bc);
        warp_sum2(term, nv);
        if (lane == 0) {
            const float bce = __fdividef(bs, fmaxf(bc, 1.0f));
            out[0] = bce + GW * __fdividef(term, fmaxf(nv, 1.0f));
            /* self-reset for graph replay (all CTAs already passed counters) */
            #pragma unroll
            for (int i = 0; i < BB; ++i) g_barA[i] = 0;
            g_done = 0;
        }
    }
}

extern "C" void kernel_launch(void* const* d_in, const int* in_sizes, int n_in,
                              void* d_out, int out_size)
{
    const float4* logits        = (const float4*)d_in[0];
    const float4* targets       = (const float4*)d_in[1];
    const int4*   sup_mask      = (const int4*)d_in[2];
    const int4*   ign_mask      = (const int4*)d_in[3];
    const int*    kv_indices    = (const int*)d_in[4];
    const int*    kv_num_blocks = (const int*)d_in[5];
    float* out = (float*)d_out;

    fused_kernel<<<GRID, TPB>>>(logits, targets, sup_mask, ign_mask,
                                kv_indices, kv_num_blocks, out);
}